// round 1
// baseline (speedup 1.0000x reference)
#include <cuda_runtime.h>
#include <math_constants.h>

// warpLayer: out[..., 0:8] = bilinear(weight, angle-coords(image)) * 5e-4
//            out[..., 8:12] = image
//
// image:  (16,512,512,4) f32  -> npix = 4,194,304 pixels, float4 per pixel
// weight: (256,256,8) f32     -> 2 MB, L2-resident gather table
// out:    (16,512,512,12) f32 -> 3 x float4 per pixel

#define GHW 256
#define NPIX (16 * 512 * 512)

__global__ __launch_bounds__(256)
void warp_layer_kernel(const float4* __restrict__ img,
                       const float*  __restrict__ wt,
                       float4*       __restrict__ out)
{
    int p = blockIdx.x * blockDim.x + threadIdx.x;
    if (p >= NPIX) return;

    float4 im = img[p];

    // C = (pi - atan2(y, -x)) / (2*pi) * 255, clipped to [0, 254]
    const float SCALE = 255.0f / (2.0f * CUDART_PI_F);
    float c0 = (CUDART_PI_F - atan2f(im.y, -im.x)) * SCALE;
    float c1 = (CUDART_PI_F - atan2f(im.w, -im.z)) * SCALE;
    c0 = fminf(fmaxf(c0, 0.0f), 254.0f);
    c1 = fminf(fmaxf(c1, 0.0f), 254.0f);

    int   i0 = (int)c0;
    int   j0 = (int)c1;
    float w0 = c0 - (float)i0;
    float w1 = c1 - (float)j0;

    // fold 0.0005 into the 4 corner weights
    float a00 = 0.0005f * (1.0f - w0) * (1.0f - w1);
    float a10 = 0.0005f * w0 * (1.0f - w1);
    float a01 = 0.0005f * (1.0f - w0) * w1;
    float a11 = 0.0005f * w0 * w1;

    // weight[i][j][0..7]: rows i0 and i0+1, cols j0 and j0+1 are 16
    // contiguous floats per row -> 4x float4 per row, float4-aligned.
    const float4* r0 = (const float4*)(wt + ((size_t)i0 * GHW + j0) * 8);
    const float4* r1 = (const float4*)(wt + ((size_t)(i0 + 1) * GHW + j0) * 8);

    float4 v00a = __ldg(r0 + 0), v00b = __ldg(r0 + 1);
    float4 v01a = __ldg(r0 + 2), v01b = __ldg(r0 + 3);
    float4 v10a = __ldg(r1 + 0), v10b = __ldg(r1 + 1);
    float4 v11a = __ldg(r1 + 2), v11b = __ldg(r1 + 3);

    float4 o0, o1;
    o0.x = a00 * v00a.x + a10 * v10a.x + a01 * v01a.x + a11 * v11a.x;
    o0.y = a00 * v00a.y + a10 * v10a.y + a01 * v01a.y + a11 * v11a.y;
    o0.z = a00 * v00a.z + a10 * v10a.z + a01 * v01a.z + a11 * v11a.z;
    o0.w = a00 * v00a.w + a10 * v10a.w + a01 * v01a.w + a11 * v11a.w;
    o1.x = a00 * v00b.x + a10 * v10b.x + a01 * v01b.x + a11 * v11b.x;
    o1.y = a00 * v00b.y + a10 * v10b.y + a01 * v01b.y + a11 * v11b.y;
    o1.z = a00 * v00b.z + a10 * v10b.z + a01 * v01b.z + a11 * v11b.z;
    o1.w = a00 * v00b.w + a10 * v10b.w + a01 * v01b.w + a11 * v11b.w;

    size_t base = (size_t)p * 3;
    out[base + 0] = o0;
    out[base + 1] = o1;
    out[base + 2] = im;
}

extern "C" void kernel_launch(void* const* d_in, const int* in_sizes, int n_in,
                              void* d_out, int out_size)
{
    const float4* img = (const float4*)d_in[0];
    const float*  wt  = (const float*)d_in[1];
    float4*       out = (float4*)d_out;

    int threads = 256;
    int blocks  = (NPIX + threads - 1) / threads;
    warp_layer_kernel<<<blocks, threads>>>(img, wt, out);
}

// round 2
// speedup vs baseline: 1.6530x; 1.6530x over previous
#include <cuda_runtime.h>
#include <math_constants.h>

// warpLayer: out[..., 0:8] = bilinear(weight, angle-coords(image)) * 5e-4
//            out[..., 8:12] = image
//
// Cooperative-gather version: 4 lanes per pixel fetch the 2x2x8 corner data,
// cutting divergent-LDG L1 wavefronts from ~256/warp to the ~96/warp floor.

#define GHW 256
#define NPIX (16 * 512 * 512)

__global__ __launch_bounds__(256)
void warp_layer_kernel(const float4* __restrict__ img,
                       const float*  __restrict__ wt,
                       float4*       __restrict__ out)
{
    const unsigned FULL = 0xffffffffu;
    int lane = threadIdx.x & 31;
    int warp = (blockIdx.x * blockDim.x + threadIdx.x) >> 5;
    int pbase = warp << 5;            // 32 pixels per warp
    int P = pbase + lane;             // this lane's own pixel

    // ---- phase 1: own pixel -> angle coords, store image passthrough ----
    float4 im = img[P];

    const float SCALE = 255.0f / (2.0f * CUDART_PI_F);
    float c0 = (CUDART_PI_F - atan2f(im.y, -im.x)) * SCALE;
    float c1 = (CUDART_PI_F - atan2f(im.w, -im.z)) * SCALE;
    c0 = fminf(fmaxf(c0, 0.0f), 254.0f);
    c1 = fminf(fmaxf(c1, 0.0f), 254.0f);

    out[(size_t)P * 3 + 2] = im;      // image passthrough

    // ---- phase 2: cooperative gather. group = lane>>2 (8 pixels/round),
    // k = lane&3: bit0 = channel half, bit1 = column (j0 / j0+1).
    int k     = lane & 3;
    int group = lane >> 2;
    int kcol  = (k >> 1) & 1;
    int khalf = k & 1;

    #pragma unroll
    for (int r = 0; r < 4; r++) {
        int src = r * 8 + group;                 // owner lane of this group's pixel
        float c0o = __shfl_sync(FULL, c0, src);
        float c1o = __shfl_sync(FULL, c1, src);

        int   i0 = (int)c0o;
        int   j0 = (int)c1o;
        float w0 = c0o - (float)i0;
        float w1 = c1o - (float)j0;

        // this lane's chunk: rows i0 and i0+1, column j0+kcol, half khalf
        int off0 = ((i0 * GHW + j0 + kcol) << 3) + (khalf << 2);
        const float4* p0 = (const float4*)(wt + off0);
        const float4* p1 = (const float4*)(wt + off0 + GHW * 8);
        float4 v0 = __ldg(p0);
        float4 v1 = __ldg(p1);

        float wcol = kcol ? w1 : (1.0f - w1);
        float s0 = 0.0005f * wcol * (1.0f - w0);
        float s1 = 0.0005f * wcol * w0;

        float4 acc;
        acc.x = s0 * v0.x + s1 * v1.x;
        acc.y = s0 * v0.y + s1 * v1.y;
        acc.z = s0 * v0.z + s1 * v1.z;
        acc.w = s0 * v0.w + s1 * v1.w;

        // sum the two columns: pair lanes k and k^2 (same channel half)
        acc.x += __shfl_xor_sync(FULL, acc.x, 2);
        acc.y += __shfl_xor_sync(FULL, acc.y, 2);
        acc.z += __shfl_xor_sync(FULL, acc.z, 2);
        acc.w += __shfl_xor_sync(FULL, acc.w, 2);

        // lanes k=0 (ch0-3) and k=1 (ch4-7) store the owner's W
        if (k < 2) {
            int Pown = pbase + r * 8 + group;
            out[(size_t)Pown * 3 + khalf] = acc;
        }
    }
}

extern "C" void kernel_launch(void* const* d_in, const int* in_sizes, int n_in,
                              void* d_out, int out_size)
{
    const float4* img = (const float4*)d_in[0];
    const float*  wt  = (const float*)d_in[1];
    float4*       out = (float4*)d_out;

    int threads = 256;
    int blocks  = NPIX / threads;     // 4194304 / 256 = 16384, exact
    warp_layer_kernel<<<blocks, threads>>>(img, wt, out);
}

// round 3
// speedup vs baseline: 1.8341x; 1.1096x over previous
#include <cuda_runtime.h>
#include <cuda_fp16.h>
#include <math_constants.h>

// warpLayer, round 3: precomputed fp16 corner table.
//
// Prologue kernel packs weight into T[cell(i,j)] = 64 bytes =
//   {corner(0,0)[8ch], corner(0,1)[8ch], corner(1,0)[8ch], corner(1,1)[8ch]} fp16.
// Main kernel: 4 lanes per pixel each grab one 16B corner chunk (the whole
// pixel gather = ONE 64B-aligned chunk = one L1 line), weighted xor-reduce,
// single predicated coalesced store of {W0, W1, im} per pixel.

#define GHW   256
#define NPIX  (16 * 512 * 512)
#define NCELL (255 * 255)

__device__ uint4 g_tab[NCELL * 4];   // 4.16 MB, 64 B per cell

__global__ __launch_bounds__(256)
void build_tab(const float* __restrict__ wt)
{
    int idx = blockIdx.x * blockDim.x + threadIdx.x;
    if (idx >= NCELL * 4) return;
    int cell = idx >> 2, t = idx & 3;          // t = corner: (t>>1, t&1)
    int i = cell / 255;
    int j = cell - i * 255;
    const float* s = wt + (((i + (t >> 1)) << 8) + j + (t & 1)) * 8;
    float4 a = *(const float4*)s;
    float4 b = *(const float4*)(s + 4);
    __half2 h0 = __floats2half2_rn(a.x, a.y);
    __half2 h1 = __floats2half2_rn(a.z, a.w);
    __half2 h2 = __floats2half2_rn(b.x, b.y);
    __half2 h3 = __floats2half2_rn(b.z, b.w);
    uint4 o;
    o.x = *reinterpret_cast<unsigned*>(&h0);
    o.y = *reinterpret_cast<unsigned*>(&h1);
    o.z = *reinterpret_cast<unsigned*>(&h2);
    o.w = *reinterpret_cast<unsigned*>(&h3);
    g_tab[idx] = o;
}

__global__ __launch_bounds__(256)
void warp_main(const float4* __restrict__ img, float4* __restrict__ out)
{
    const unsigned FULL = 0xffffffffu;
    int lane  = threadIdx.x & 31;
    int warp  = (blockIdx.x * blockDim.x + threadIdx.x) >> 5;
    int pbase = warp << 5;

    // own pixel -> angle coords
    float4 im = img[pbase + lane];
    const float SCALE = 255.0f / (2.0f * CUDART_PI_F);
    float c0 = (CUDART_PI_F - atan2f(im.y, -im.x)) * SCALE;
    float c1 = (CUDART_PI_F - atan2f(im.w, -im.z)) * SCALE;
    c0 = fminf(fmaxf(c0, 0.0f), 254.0f);
    c1 = fminf(fmaxf(c1, 0.0f), 254.0f);

    int k  = lane & 3;        // corner id: row = k>>1, col = k&1
    int g  = lane >> 2;       // pixel-in-round (0..7)
    int kr = k >> 1, kc = k & 1;

    #pragma unroll
    for (int r = 0; r < 4; r++) {
        int q = r * 8 + g;                       // warp-pixel index
        float c0o = __shfl_sync(FULL, c0, q);
        float c1o = __shfl_sync(FULL, c1, q);

        int   i0 = (int)c0o;
        int   j0 = (int)c1o;
        float w0 = c0o - (float)i0;
        float w1 = c1o - (float)j0;
        float a  = (kr ? w0 : 1.0f - w0) * (kc ? w1 : 1.0f - w1) * 0.0005f;

        uint4 v = __ldg(&g_tab[((i0 * 255 + j0) << 2) + k]);
        float2 f0 = __half22float2(*reinterpret_cast<__half2*>(&v.x));
        float2 f1 = __half22float2(*reinterpret_cast<__half2*>(&v.y));
        float2 f2 = __half22float2(*reinterpret_cast<__half2*>(&v.z));
        float2 f3 = __half22float2(*reinterpret_cast<__half2*>(&v.w));

        float p[8];
        p[0] = a * f0.x; p[1] = a * f0.y; p[2] = a * f1.x; p[3] = a * f1.y;
        p[4] = a * f2.x; p[5] = a * f2.y; p[6] = a * f3.x; p[7] = a * f3.y;

        // step A: combine the two columns (xor 1), all 8 comps
        #pragma unroll
        for (int c = 0; c < 8; c++)
            p[c] += __shfl_xor_sync(FULL, p[c], 1);

        // step B: route halves — lanes with k&1 take comps 4..7
        float u[4];
        #pragma unroll
        for (int c = 0; c < 4; c++)
            u[c] = (k & 1) ? p[c + 4] : p[c];

        // step C: combine the two rows (xor 2)
        #pragma unroll
        for (int c = 0; c < 4; c++)
            u[c] += __shfl_xor_sync(FULL, u[c], 2);

        // lanes: k=0 -> W[0:4], k=1 -> W[4:8], k=2 -> image passthrough
        int Pown = pbase + q;
        float4 sv;
        if (k == 2) sv = __ldg(&img[Pown]);            // L1-hot reload, 1 line
        else        sv = make_float4(u[0], u[1], u[2], u[3]);
        if (k < 3)  out[(size_t)Pown * 3 + k] = sv;    // 24 lanes, 384B contig
    }
}

extern "C" void kernel_launch(void* const* d_in, const int* in_sizes, int n_in,
                              void* d_out, int out_size)
{
    const float4* img = (const float4*)d_in[0];
    const float*  wt  = (const float*)d_in[1];
    float4*       out = (float4*)d_out;

    build_tab<<<(NCELL * 4 + 255) / 256, 256>>>(wt);
    warp_main<<<NPIX / 256, 256>>>(img, out);
}

// round 4
// speedup vs baseline: 2.0679x; 1.1274x over previous
#include <cuda_runtime.h>
#include <cuda_fp16.h>
#include <math_constants.h>

// warpLayer, round 4: fp16 corner table + half2 xor-reduction (min SHFL).
//
// build_tab: T[cell(i,j)] = 64B = 4 corners x 8ch fp16 (one L1 line / pixel).
// warp_main: 4 lanes per pixel gather one 16B corner chunk each, reduce in
// half2 (4+2 SHFLs instead of 8+4), single predicated coalesced store.

#define GHW   256
#define NPIX  (16 * 512 * 512)
#define NCELL (255 * 255)

__device__ uint4 g_tab[NCELL * 4];   // 4.16 MB

__global__ __launch_bounds__(256)
void build_tab(const float* __restrict__ wt)
{
    int idx = blockIdx.x * blockDim.x + threadIdx.x;
    if (idx >= NCELL * 4) return;
    int cell = idx >> 2, t = idx & 3;          // corner (t>>1, t&1)
    int i = cell / 255;
    int j = cell - i * 255;
    const float* s = wt + (((i + (t >> 1)) << 8) + j + (t & 1)) * 8;
    float4 a = *(const float4*)s;
    float4 b = *(const float4*)(s + 4);
    __half2 h0 = __floats2half2_rn(a.x, a.y);
    __half2 h1 = __floats2half2_rn(a.z, a.w);
    __half2 h2 = __floats2half2_rn(b.x, b.y);
    __half2 h3 = __floats2half2_rn(b.z, b.w);
    uint4 o;
    o.x = *reinterpret_cast<unsigned*>(&h0);
    o.y = *reinterpret_cast<unsigned*>(&h1);
    o.z = *reinterpret_cast<unsigned*>(&h2);
    o.w = *reinterpret_cast<unsigned*>(&h3);
    g_tab[idx] = o;
}

__device__ __forceinline__ __half2 shfl_h2(unsigned mask, __half2 v, int xr)
{
    unsigned u = *reinterpret_cast<unsigned*>(&v);
    u = __shfl_xor_sync(mask, u, xr);
    return *reinterpret_cast<__half2*>(&u);
}

__global__ __launch_bounds__(256)
void warp_main(const float4* __restrict__ img, float4* __restrict__ out)
{
    const unsigned FULL = 0xffffffffu;
    int lane  = threadIdx.x & 31;
    int warp  = (blockIdx.x * blockDim.x + threadIdx.x) >> 5;
    int pbase = warp << 5;

    // ---- own pixel: angle coords -> (cell, packed w) ----
    float4 im = img[pbase + lane];
    const float SCALE = 255.0f / (2.0f * CUDART_PI_F);
    float c0 = (CUDART_PI_F - atan2f(im.y, -im.x)) * SCALE;
    float c1 = (CUDART_PI_F - atan2f(im.w, -im.z)) * SCALE;
    c0 = fminf(fmaxf(c0, 0.0f), 254.0f);
    c1 = fminf(fmaxf(c1, 0.0f), 254.0f);

    int   i0 = (int)c0;
    int   j0 = (int)c1;
    int   my_cell = i0 * 255 + j0;
    __half2 wp = __floats2half2_rn(c0 - (float)i0, c1 - (float)j0);
    unsigned my_w = *reinterpret_cast<unsigned*>(&wp);

    int k  = lane & 3;        // corner: row = k>>1, col = k&1
    int g  = lane >> 2;       // pixel-in-round
    int kr = k >> 1, kc = k & 1;

    #pragma unroll
    for (int r = 0; r < 4; r++) {
        int q = r * 8 + g;
        int      cell = __shfl_sync(FULL, my_cell, q);
        unsigned wub  = __shfl_sync(FULL, my_w, q);
        float2 wf = __half22float2(*reinterpret_cast<__half2*>(&wub));

        float a = (kr ? wf.x : 1.0f - wf.x) * (kc ? wf.y : 1.0f - wf.y);
        __half2 ah = __half2half2(__float2half_rn(a));

        uint4 v = __ldg(&g_tab[(cell << 2) + k]);
        __half2 p0 = __hmul2(ah, *reinterpret_cast<__half2*>(&v.x)); // ch01
        __half2 p1 = __hmul2(ah, *reinterpret_cast<__half2*>(&v.y)); // ch23
        __half2 p2 = __hmul2(ah, *reinterpret_cast<__half2*>(&v.z)); // ch45
        __half2 p3 = __hmul2(ah, *reinterpret_cast<__half2*>(&v.w)); // ch67

        // step A: combine columns (xor 1)
        p0 = __hadd2(p0, shfl_h2(FULL, p0, 1));
        p1 = __hadd2(p1, shfl_h2(FULL, p1, 1));
        p2 = __hadd2(p2, shfl_h2(FULL, p2, 1));
        p3 = __hadd2(p3, shfl_h2(FULL, p3, 1));

        // route halves: odd k takes ch45/ch67
        __half2 u0 = (k & 1) ? p2 : p0;
        __half2 u1 = (k & 1) ? p3 : p1;

        // step C: combine rows (xor 2)
        u0 = __hadd2(u0, shfl_h2(FULL, u0, 2));
        u1 = __hadd2(u1, shfl_h2(FULL, u1, 2));

        // lanes: k=0 -> W[0:4], k=1 -> W[4:8], k=2 -> image passthrough
        int Pown = pbase + q;
        float4 sv;
        if (k == 2) {
            sv = __ldg(&img[Pown]);
        } else {
            float2 lo = __half22float2(u0);
            float2 hi = __half22float2(u1);
            sv = make_float4(lo.x * 0.0005f, lo.y * 0.0005f,
                             hi.x * 0.0005f, hi.y * 0.0005f);
        }
        if (k < 3) out[(size_t)Pown * 3 + k] = sv;
    }
}

extern "C" void kernel_launch(void* const* d_in, const int* in_sizes, int n_in,
                              void* d_out, int out_size)
{
    const float4* img = (const float4*)d_in[0];
    const float*  wt  = (const float*)d_in[1];
    float4*       out = (float4*)d_out;

    build_tab<<<(NCELL * 4 + 255) / 256, 256>>>(wt);
    warp_main<<<NPIX / 256, 256>>>(img, out);
}

// round 5
// speedup vs baseline: 2.1443x; 1.0370x over previous
#include <cuda_runtime.h>
#include <cuda_fp16.h>
#include <math_constants.h>

// warpLayer, round 5: channel-major fp16 corner table -> in-lane bilinear.
//
// Cell (64B) = 4 chunks of 16B; chunk k = {c00,c01,c10,c11} as half2 pairs
// holding channels [2k, 2k+1]. Lane k of a 4-lane group computes channels
// 2k..2k+1 of the group's pixel entirely in-lane: no reduction shuffles.

#define NPIX  (16 * 512 * 512)
#define NCELL (255 * 255)

__device__ uint4 g_tab[NCELL * 4];   // 4.16 MB, channel-major cells

__global__ __launch_bounds__(256)
void build_tab(const float* __restrict__ wt)
{
    int idx = blockIdx.x * blockDim.x + threadIdx.x;
    if (idx >= NCELL * 4) return;
    int cell = idx >> 2, k = idx & 3;           // k = channel pair
    int i = cell / 255;
    int j = cell - i * 255;
    const float* base = wt + ((i << 8) + j) * 8 + (k << 1);
    float2 c00 = *(const float2*)(base);
    float2 c01 = *(const float2*)(base + 8);
    float2 c10 = *(const float2*)(base + 256 * 8);
    float2 c11 = *(const float2*)(base + 256 * 8 + 8);
    __half2 h00 = __floats2half2_rn(c00.x, c00.y);
    __half2 h01 = __floats2half2_rn(c01.x, c01.y);
    __half2 h10 = __floats2half2_rn(c10.x, c10.y);
    __half2 h11 = __floats2half2_rn(c11.x, c11.y);
    uint4 o;
    o.x = *reinterpret_cast<unsigned*>(&h00);
    o.y = *reinterpret_cast<unsigned*>(&h01);
    o.z = *reinterpret_cast<unsigned*>(&h10);
    o.w = *reinterpret_cast<unsigned*>(&h11);
    g_tab[idx] = o;
}

__global__ __launch_bounds__(256)
void warp_main(const float4* __restrict__ img, float* __restrict__ out)
{
    const unsigned FULL = 0xffffffffu;
    int lane  = threadIdx.x & 31;
    int warp  = (blockIdx.x * blockDim.x + threadIdx.x) >> 5;
    int pbase = warp << 5;
    int P     = pbase + lane;

    // ---- own pixel: angle coords -> (cell, packed frac) ----
    float4 im = img[P];
    const float SCALE = 255.0f / (2.0f * CUDART_PI_F);
    float c0 = (CUDART_PI_F - atan2f(im.y, -im.x)) * SCALE;
    float c1 = (CUDART_PI_F - atan2f(im.w, -im.z)) * SCALE;
    c0 = fminf(fmaxf(c0, 0.0f), 254.0f);
    c1 = fminf(fmaxf(c1, 0.0f), 254.0f);

    int i0 = (int)c0;
    int j0 = (int)c1;
    int my_cell = i0 * 255 + j0;
    __half2 wp = __floats2half2_rn(c0 - (float)i0, c1 - (float)j0);
    unsigned my_w = *reinterpret_cast<unsigned*>(&wp);

    int k = lane & 3;         // channel pair owned by this lane
    int g = lane >> 2;        // pixel-in-round

    #pragma unroll
    for (int r = 0; r < 4; r++) {
        int q = r * 8 + g;
        int      cell = __shfl_sync(FULL, my_cell, q);
        unsigned wub  = __shfl_sync(FULL, my_w, q);
        float2 wf = __half22float2(*reinterpret_cast<__half2*>(&wub));

        // bilinear corner weights, 0.0005 folded in
        float u0 = 0.0005f * (1.0f - wf.x);
        float u1 = 0.0005f * wf.x;
        float a00 = u0 * (1.0f - wf.y);
        float a01 = u0 * wf.y;
        float a10 = u1 * (1.0f - wf.y);
        float a11 = u1 * wf.y;

        uint4 v = __ldg(&g_tab[(cell << 2) + k]);
        float2 f00 = __half22float2(*reinterpret_cast<__half2*>(&v.x));
        float2 f01 = __half22float2(*reinterpret_cast<__half2*>(&v.y));
        float2 f10 = __half22float2(*reinterpret_cast<__half2*>(&v.z));
        float2 f11 = __half22float2(*reinterpret_cast<__half2*>(&v.w));

        float2 res;
        res.x = a00 * f00.x + a01 * f01.x + a10 * f10.x + a11 * f11.x;
        res.y = a00 * f00.y + a01 * f01.y + a10 * f10.y + a11 * f11.y;

        // lane (k,g) stores channels 2k..2k+1 of pixel q
        *(float2*)(out + (size_t)(pbase + q) * 12 + (k << 1)) = res;
    }

    // image passthrough: own pixel, channels 8..11
    *(float4*)(out + (size_t)P * 12 + 8) = im;
}

extern "C" void kernel_launch(void* const* d_in, const int* in_sizes, int n_in,
                              void* d_out, int out_size)
{
    const float4* img = (const float4*)d_in[0];
    const float*  wt  = (const float*)d_in[1];
    float*        out = (float*)d_out;

    build_tab<<<(NCELL * 4 + 255) / 256, 256>>>(wt);
    warp_main<<<NPIX / 256, 256>>>(img, out);
}

// round 6
// speedup vs baseline: 2.2080x; 1.0297x over previous
#include <cuda_runtime.h>
#include <cuda_fp16.h>
#include <math_constants.h>

// warpLayer, round 6: channel-major fp16 table (permuted chunks) + in-lane
// bilinear + one xor-2 pair exchange -> fully contiguous float4 stores.
//
// Cell (64B) = 4 chunks of 16B; chunk k holds 4 corners (half2 each) of
// channel-pair perm[k], perm = {0,2,1,3} -> k=0:ch01, k=1:ch45, k=2:ch23,
// k=3:ch67. After bilinear, shfl_xor(2) gives k=0 -> W[0:4], k=1 -> W[4:8].

#define NPIX  (16 * 512 * 512)
#define NCELL (255 * 255)

__device__ uint4 g_tab[NCELL * 4];   // 4.16 MB

__global__ __launch_bounds__(256)
void build_tab(const float* __restrict__ wt)
{
    int idx = blockIdx.x * blockDim.x + threadIdx.x;
    if (idx >= NCELL * 4) return;
    int cell = idx >> 2, k = idx & 3;
    int cp = (k == 1) ? 2 : (k == 2) ? 1 : k;   // perm = {0,2,1,3}
    int i = cell / 255;
    int j = cell - i * 255;
    const float* base = wt + ((i << 8) + j) * 8 + (cp << 1);
    float2 c00 = *(const float2*)(base);
    float2 c01 = *(const float2*)(base + 8);
    float2 c10 = *(const float2*)(base + 256 * 8);
    float2 c11 = *(const float2*)(base + 256 * 8 + 8);
    __half2 h00 = __floats2half2_rn(c00.x, c00.y);
    __half2 h01 = __floats2half2_rn(c01.x, c01.y);
    __half2 h10 = __floats2half2_rn(c10.x, c10.y);
    __half2 h11 = __floats2half2_rn(c11.x, c11.y);
    uint4 o;
    o.x = *reinterpret_cast<unsigned*>(&h00);
    o.y = *reinterpret_cast<unsigned*>(&h01);
    o.z = *reinterpret_cast<unsigned*>(&h10);
    o.w = *reinterpret_cast<unsigned*>(&h11);
    g_tab[idx] = o;
}

__global__ __launch_bounds__(256)
void warp_main(const float4* __restrict__ img, float4* __restrict__ out)
{
    const unsigned FULL = 0xffffffffu;
    int lane  = threadIdx.x & 31;
    int warp  = (blockIdx.x * blockDim.x + threadIdx.x) >> 5;
    int pbase = warp << 5;
    int P     = pbase + lane;

    // ---- own pixel: angle coords -> (cell, packed frac) ----
    float4 im = img[P];
    const float SCALE = 255.0f / (2.0f * CUDART_PI_F);
    float c0 = (CUDART_PI_F - atan2f(im.y, -im.x)) * SCALE;
    float c1 = (CUDART_PI_F - atan2f(im.w, -im.z)) * SCALE;
    c0 = fminf(fmaxf(c0, 0.0f), 254.0f);
    c1 = fminf(fmaxf(c1, 0.0f), 254.0f);

    int i0 = (int)c0;
    int j0 = (int)c1;
    int my_cell = i0 * 255 + j0;
    __half2 wp = __floats2half2_rn(c0 - (float)i0, c1 - (float)j0);
    unsigned my_w = *reinterpret_cast<unsigned*>(&wp);

    int k = lane & 3;         // chunk / role id
    int g = lane >> 2;        // pixel-in-round

    #pragma unroll
    for (int r = 0; r < 4; r++) {
        int q = r * 8 + g;
        int      cell = __shfl_sync(FULL, my_cell, q);
        unsigned wub  = __shfl_sync(FULL, my_w, q);
        float2 wf = __half22float2(*reinterpret_cast<__half2*>(&wub));

        float u0  = 0.0005f * (1.0f - wf.x);
        float u1  = 0.0005f * wf.x;
        float a00 = u0 * (1.0f - wf.y);
        float a01 = u0 * wf.y;
        float a10 = u1 * (1.0f - wf.y);
        float a11 = u1 * wf.y;

        uint4 v = __ldg(&g_tab[(cell << 2) + k]);
        float2 f00 = __half22float2(*reinterpret_cast<__half2*>(&v.x));
        float2 f01 = __half22float2(*reinterpret_cast<__half2*>(&v.y));
        float2 f10 = __half22float2(*reinterpret_cast<__half2*>(&v.z));
        float2 f11 = __half22float2(*reinterpret_cast<__half2*>(&v.w));

        float rx = a00 * f00.x + a01 * f01.x + a10 * f10.x + a11 * f11.x;
        float ry = a00 * f00.y + a01 * f01.y + a10 * f10.y + a11 * f11.y;

        // pair exchange: k=0 <-> k=2 (ch01 <-> ch23), k=1 <-> k=3 (ch45 <-> ch67)
        float ox = __shfl_xor_sync(FULL, rx, 2);
        float oy = __shfl_xor_sync(FULL, ry, 2);

        int Pown = pbase + q;
        float4 sv;
        if (k == 2) sv = __ldg(&img[Pown]);               // L1-hot, 128B/round
        else        sv = make_float4(rx, ry, ox, oy);     // k=0:W[0:4], k=1:W[4:8]
        if (k < 3)  out[(size_t)Pown * 3 + k] = sv;       // 24 lanes, 384B contig
    }
}

extern "C" void kernel_launch(void* const* d_in, const int* in_sizes, int n_in,
                              void* d_out, int out_size)
{
    const float4* img = (const float4*)d_in[0];
    const float*  wt  = (const float*)d_in[1];
    float4*       out = (float4*)d_out;

    build_tab<<<(NCELL * 4 + 255) / 256, 256>>>(wt);
    warp_main<<<NPIX / 256, 256>>>(img, out);
}

// round 7
// speedup vs baseline: 2.2769x; 1.0312x over previous
#include <cuda_runtime.h>
#include <cuda_fp16.h>
#include <math_constants.h>

// warpLayer, round 7: custom atan2 (C-units) + owner-packed half2 weights +
// HFMA2 bilinear on the permuted channel-major fp16 table (x0.0005 folded).

#define NPIX  (16 * 512 * 512)
#define NCELL (255 * 255)

__device__ uint4 g_tab[NCELL * 4];   // 4.16 MB

__global__ __launch_bounds__(256)
void build_tab(const float* __restrict__ wt)
{
    int idx = blockIdx.x * blockDim.x + threadIdx.x;
    if (idx >= NCELL * 4) return;
    int cell = idx >> 2, k = idx & 3;
    int cp = (k == 1) ? 2 : (k == 2) ? 1 : k;   // perm {0,2,1,3}
    int i = cell / 255;
    int j = cell - i * 255;
    const float* base = wt + ((i << 8) + j) * 8 + (cp << 1);
    float2 c00 = *(const float2*)(base);
    float2 c01 = *(const float2*)(base + 8);
    float2 c10 = *(const float2*)(base + 256 * 8);
    float2 c11 = *(const float2*)(base + 256 * 8 + 8);
    const float S = 0.0005f;
    __half2 h00 = __floats2half2_rn(S * c00.x, S * c00.y);
    __half2 h01 = __floats2half2_rn(S * c01.x, S * c01.y);
    __half2 h10 = __floats2half2_rn(S * c10.x, S * c10.y);
    __half2 h11 = __floats2half2_rn(S * c11.x, S * c11.y);
    uint4 o;
    o.x = *reinterpret_cast<unsigned*>(&h00);
    o.y = *reinterpret_cast<unsigned*>(&h01);
    o.z = *reinterpret_cast<unsigned*>(&h10);
    o.w = *reinterpret_cast<unsigned*>(&h11);
    g_tab[idx] = o;
}

// C = wrap(atan2(y, x)) * 255/(2*pi)  in [0, 255]
__device__ __forceinline__ float angle_c(float y, float x)
{
    const float K = 255.0f / (2.0f * CUDART_PI_F);
    float ax = fabsf(x), ay = fabsf(y);
    float mx = fmaxf(ax, ay), mn = fminf(ax, ay);
    float a  = __fdividef(mn, mx);
    float s  = a * a;
    float p  =            -0.01172120f;
    p = fmaf(p, s,  0.05265332f);
    p = fmaf(p, s, -0.11643287f);
    p = fmaf(p, s,  0.19354346f);
    p = fmaf(p, s, -0.33262347f);
    p = fmaf(p, s,  0.99997726f);
    float r = a * p * K;                 // [0, 63.75]
    if (ay > ax)  r = 63.75f - r;
    if (x < 0.0f) r = 127.5f - r;
    if (y < 0.0f) r = 255.0f - r;
    return r;
}

__global__ __launch_bounds__(256)
void warp_main(const float4* __restrict__ img, float4* __restrict__ out)
{
    const unsigned FULL = 0xffffffffu;
    int lane  = threadIdx.x & 31;
    int warp  = (blockIdx.x * blockDim.x + threadIdx.x) >> 5;
    int pbase = warp << 5;
    int P     = pbase + lane;

    // ---- prologue: own pixel -> cell + packed bilinear weights ----
    float4 im = img[P];
    float c0 = fminf(angle_c(im.y, im.x), 254.0f);
    float c1 = fminf(angle_c(im.w, im.z), 254.0f);

    float fi = floorf(c0);
    float fj = floorf(c1);
    int my_cell = (int)fi * 255 + (int)fj;
    float w0 = c0 - fi, w1 = c1 - fj;
    __half2 pk0 = __floats2half2_rn((1.0f - w0) * (1.0f - w1),   // w00
                                    (1.0f - w0) * w1);           // w01
    __half2 pk1 = __floats2half2_rn(w0 * (1.0f - w1),            // w10
                                    w0 * w1);                    // w11
    unsigned pu0 = *reinterpret_cast<unsigned*>(&pk0);
    unsigned pu1 = *reinterpret_cast<unsigned*>(&pk1);

    int k = lane & 3;         // chunk / role id
    int g = lane >> 2;        // pixel-in-round

    #pragma unroll
    for (int r = 0; r < 4; r++) {
        int q = r * 8 + g;
        int      cell = __shfl_sync(FULL, my_cell, q);
        unsigned b0   = __shfl_sync(FULL, pu0, q);
        unsigned b1   = __shfl_sync(FULL, pu1, q);
        __half2 v0 = *reinterpret_cast<__half2*>(&b0);
        __half2 v1 = *reinterpret_cast<__half2*>(&b1);
        __half2 A00 = __low2half2(v0),  A01 = __high2half2(v0);
        __half2 A10 = __low2half2(v1),  A11 = __high2half2(v1);

        uint4 v = __ldg(&g_tab[(cell << 2) + k]);
        __half2 acc = __hmul2(A00, *reinterpret_cast<__half2*>(&v.x));
        acc = __hfma2(A01, *reinterpret_cast<__half2*>(&v.y), acc);
        acc = __hfma2(A10, *reinterpret_cast<__half2*>(&v.z), acc);
        acc = __hfma2(A11, *reinterpret_cast<__half2*>(&v.w), acc);

        float2 rf = __half22float2(acc);
        // pair exchange: k=0<->2 (ch01<->ch23), k=1<->3 (ch45<->ch67)
        float ox = __shfl_xor_sync(FULL, rf.x, 2);
        float oy = __shfl_xor_sync(FULL, rf.y, 2);

        int Pown = pbase + q;
        float4 sv;
        if (k == 2) sv = __ldg(&img[Pown]);               // L1-hot reload
        else        sv = make_float4(rf.x, rf.y, ox, oy); // k=0:W[0:4], k=1:W[4:8]
        if (k < 3)  out[(size_t)Pown * 3 + k] = sv;       // 384B contiguous
    }
}

extern "C" void kernel_launch(void* const* d_in, const int* in_sizes, int n_in,
                              void* d_out, int out_size)
{
    const float4* img = (const float4*)d_in[0];
    const float*  wt  = (const float*)d_in[1];
    float4*       out = (float4*)d_out;

    build_tab<<<(NCELL * 4 + 255) / 256, 256>>>(wt);
    warp_main<<<NPIX / 256, 256>>>(img, out);
}

// round 8
// speedup vs baseline: 2.3320x; 1.0242x over previous
#include <cuda_runtime.h>
#include <cuda_fp16.h>
#include <math_constants.h>

// warpLayer, round 8: same channel-major fp16 table + in-lane HFMA2 bilinear,
// now 2 pixels per thread (64/warp) for doubled memory-level parallelism.

#define NPIX  (16 * 512 * 512)
#define NCELL (255 * 255)

__device__ uint4 g_tab[NCELL * 4];   // 4.16 MB

__global__ __launch_bounds__(256)
void build_tab(const float* __restrict__ wt)
{
    int idx = blockIdx.x * blockDim.x + threadIdx.x;
    if (idx >= NCELL * 4) return;
    int cell = idx >> 2, k = idx & 3;
    int cp = (k == 1) ? 2 : (k == 2) ? 1 : k;   // perm {0,2,1,3}
    int i = cell / 255;
    int j = cell - i * 255;
    const float* base = wt + ((i << 8) + j) * 8 + (cp << 1);
    float2 c00 = *(const float2*)(base);
    float2 c01 = *(const float2*)(base + 8);
    float2 c10 = *(const float2*)(base + 256 * 8);
    float2 c11 = *(const float2*)(base + 256 * 8 + 8);
    const float S = 0.0005f;
    __half2 h00 = __floats2half2_rn(S * c00.x, S * c00.y);
    __half2 h01 = __floats2half2_rn(S * c01.x, S * c01.y);
    __half2 h10 = __floats2half2_rn(S * c10.x, S * c10.y);
    __half2 h11 = __floats2half2_rn(S * c11.x, S * c11.y);
    uint4 o;
    o.x = *reinterpret_cast<unsigned*>(&h00);
    o.y = *reinterpret_cast<unsigned*>(&h01);
    o.z = *reinterpret_cast<unsigned*>(&h10);
    o.w = *reinterpret_cast<unsigned*>(&h11);
    g_tab[idx] = o;
}

// C = wrap(atan2(y, x)) * 255/(2*pi) in [0, 255]
__device__ __forceinline__ float angle_c(float y, float x)
{
    const float K = 255.0f / (2.0f * CUDART_PI_F);
    float ax = fabsf(x), ay = fabsf(y);
    float mx = fmaxf(ax, ay), mn = fminf(ax, ay);
    float a  = __fdividef(mn, mx);
    float s  = a * a;
    float p  =            -0.01172120f;
    p = fmaf(p, s,  0.05265332f);
    p = fmaf(p, s, -0.11643287f);
    p = fmaf(p, s,  0.19354346f);
    p = fmaf(p, s, -0.33262347f);
    p = fmaf(p, s,  0.99997726f);
    float r = a * p * K;
    if (ay > ax)  r = 63.75f - r;
    if (x < 0.0f) r = 127.5f - r;
    if (y < 0.0f) r = 255.0f - r;
    return r;
}

__device__ __forceinline__ void prep(const float4& im, int& cell,
                                     unsigned& w0p, unsigned& w1p)
{
    float c0 = fminf(angle_c(im.y, im.x), 254.0f);
    float c1 = fminf(angle_c(im.w, im.z), 254.0f);
    float fi = floorf(c0);
    float fj = floorf(c1);
    cell = (int)fi * 255 + (int)fj;
    float w0 = c0 - fi, w1 = c1 - fj;
    __half2 pk0 = __floats2half2_rn((1.0f - w0) * (1.0f - w1),
                                    (1.0f - w0) * w1);
    __half2 pk1 = __floats2half2_rn(w0 * (1.0f - w1), w0 * w1);
    w0p = *reinterpret_cast<unsigned*>(&pk0);
    w1p = *reinterpret_cast<unsigned*>(&pk1);
}

__device__ __forceinline__ float2 bilin(const uint4& v, unsigned b0, unsigned b1)
{
    __half2 v0 = *reinterpret_cast<const __half2*>(&b0);
    __half2 v1 = *reinterpret_cast<const __half2*>(&b1);
    __half2 acc = __hmul2(__low2half2(v0),  *reinterpret_cast<const __half2*>(&v.x));
    acc = __hfma2(__high2half2(v0), *reinterpret_cast<const __half2*>(&v.y), acc);
    acc = __hfma2(__low2half2(v1),  *reinterpret_cast<const __half2*>(&v.z), acc);
    acc = __hfma2(__high2half2(v1), *reinterpret_cast<const __half2*>(&v.w), acc);
    return __half22float2(acc);
}

__global__ __launch_bounds__(256)
void warp_main(const float4* __restrict__ img, float4* __restrict__ out)
{
    const unsigned FULL = 0xffffffffu;
    int lane  = threadIdx.x & 31;
    int warp  = (blockIdx.x * blockDim.x + threadIdx.x) >> 5;
    int pbase = warp << 6;                 // 64 pixels per warp

    float4 imA = img[pbase + lane];
    float4 imB = img[pbase + 32 + lane];

    int cA, cB; unsigned a0, a1, b0, b1;
    prep(imA, cA, a0, a1);
    prep(imB, cB, b0, b1);

    int k = lane & 3;
    int g = lane >> 2;

    #pragma unroll
    for (int r = 0; r < 4; r++) {
        int q = r * 8 + g;

        int      cellA = __shfl_sync(FULL, cA, q);
        unsigned wA0   = __shfl_sync(FULL, a0, q);
        unsigned wA1   = __shfl_sync(FULL, a1, q);
        int      cellB = __shfl_sync(FULL, cB, q);
        unsigned wB0   = __shfl_sync(FULL, b0, q);
        unsigned wB1   = __shfl_sync(FULL, b1, q);

        uint4 vA = __ldg(&g_tab[(cellA << 2) + k]);
        uint4 vB = __ldg(&g_tab[(cellB << 2) + k]);

        int PA = pbase + q;
        int PB = pbase + 32 + q;
        float4 reA, reB;
        if (k == 2) { reA = __ldg(&img[PA]); reB = __ldg(&img[PB]); }

        float2 rA = bilin(vA, wA0, wA1);
        float2 rB = bilin(vB, wB0, wB1);

        float oAx = __shfl_xor_sync(FULL, rA.x, 2);
        float oAy = __shfl_xor_sync(FULL, rA.y, 2);
        float oBx = __shfl_xor_sync(FULL, rB.x, 2);
        float oBy = __shfl_xor_sync(FULL, rB.y, 2);

        float4 svA = (k == 2) ? reA : make_float4(rA.x, rA.y, oAx, oAy);
        float4 svB = (k == 2) ? reB : make_float4(rB.x, rB.y, oBx, oBy);
        if (k < 3) {
            out[(size_t)PA * 3 + k] = svA;
            out[(size_t)PB * 3 + k] = svB;
        }
    }
}

extern "C" void kernel_launch(void* const* d_in, const int* in_sizes, int n_in,
                              void* d_out, int out_size)
{
    const float4* img = (const float4*)d_in[0];
    const float*  wt  = (const float*)d_in[1];
    float4*       out = (float4*)d_out;

    build_tab<<<(NCELL * 4 + 255) / 256, 256>>>(wt);
    warp_main<<<NPIX / 512, 256>>>(img, out);
}

// round 9
// speedup vs baseline: 2.4508x; 1.0509x over previous
#include <cuda_runtime.h>
#include <cuda_fp16.h>
#include <math_constants.h>

// warpLayer, round 9: 2 px/thread + 2-word broadcast (cell, half2 w) +
// receiver-side corner products in half2 + forced 6 blocks/SM occupancy.

#define NPIX  (16 * 512 * 512)
#define NCELL (255 * 255)

__device__ uint4 g_tab[NCELL * 4];   // 4.16 MB

__global__ __launch_bounds__(256)
void build_tab(const float* __restrict__ wt)
{
    int idx = blockIdx.x * blockDim.x + threadIdx.x;
    if (idx >= NCELL * 4) return;
    int cell = idx >> 2, k = idx & 3;
    int cp = (k == 1) ? 2 : (k == 2) ? 1 : k;   // perm {0,2,1,3}
    int i = cell / 255;
    int j = cell - i * 255;
    const float* base = wt + ((i << 8) + j) * 8 + (cp << 1);
    float2 c00 = *(const float2*)(base);
    float2 c01 = *(const float2*)(base + 8);
    float2 c10 = *(const float2*)(base + 256 * 8);
    float2 c11 = *(const float2*)(base + 256 * 8 + 8);
    const float S = 0.0005f;
    __half2 h00 = __floats2half2_rn(S * c00.x, S * c00.y);
    __half2 h01 = __floats2half2_rn(S * c01.x, S * c01.y);
    __half2 h10 = __floats2half2_rn(S * c10.x, S * c10.y);
    __half2 h11 = __floats2half2_rn(S * c11.x, S * c11.y);
    uint4 o;
    o.x = *reinterpret_cast<unsigned*>(&h00);
    o.y = *reinterpret_cast<unsigned*>(&h01);
    o.z = *reinterpret_cast<unsigned*>(&h10);
    o.w = *reinterpret_cast<unsigned*>(&h11);
    g_tab[idx] = o;
}

// C = wrap(atan2(y, x)) * 255/(2*pi) in [0, 255]
__device__ __forceinline__ float angle_c(float y, float x)
{
    const float K = 255.0f / (2.0f * CUDART_PI_F);
    float ax = fabsf(x), ay = fabsf(y);
    float mx = fmaxf(ax, ay), mn = fminf(ax, ay);
    float a  = __fdividef(mn, mx);
    float s  = a * a;
    float p  =            -0.01172120f;
    p = fmaf(p, s,  0.05265332f);
    p = fmaf(p, s, -0.11643287f);
    p = fmaf(p, s,  0.19354346f);
    p = fmaf(p, s, -0.33262347f);
    p = fmaf(p, s,  0.99997726f);
    float r = a * p * K;
    if (ay > ax)  r = 63.75f - r;
    if (x < 0.0f) r = 127.5f - r;
    if (y < 0.0f) r = 255.0f - r;
    return r;
}

__device__ __forceinline__ void prep(const float4& im, int& cell, unsigned& wp)
{
    float c0 = fminf(angle_c(im.y, im.x), 254.0f);
    float c1 = fminf(angle_c(im.w, im.z), 254.0f);
    float fi = floorf(c0);
    float fj = floorf(c1);
    cell = (int)fi * 255 + (int)fj;
    __half2 h = __floats2half2_rn(c0 - fi, c1 - fj);
    wp = *reinterpret_cast<unsigned*>(&h);
}

// from packed (w0,w1) build corner-product pairs and do the bilinear
__device__ __forceinline__ float2 bilin(const uint4& v, unsigned wu)
{
    __half2 h  = *reinterpret_cast<const __half2*>(&wu);       // (w0, w1)
    __half2 om = __hsub2(__float2half2_rn(1.0f), h);           // (1-w0, 1-w1)
    __half2 p  = __halves2half2(__high2half(om), __high2half(h)); // (1-w1, w1)
    __half2 A0 = __hmul2(__low2half2(om), p);  // (a00, a01)
    __half2 A1 = __hmul2(__low2half2(h),  p);  // (a10, a11)

    __half2 acc = __hmul2(__low2half2(A0),  *reinterpret_cast<const __half2*>(&v.x));
    acc = __hfma2(__high2half2(A0), *reinterpret_cast<const __half2*>(&v.y), acc);
    acc = __hfma2(__low2half2(A1),  *reinterpret_cast<const __half2*>(&v.z), acc);
    acc = __hfma2(__high2half2(A1), *reinterpret_cast<const __half2*>(&v.w), acc);
    return __half22float2(acc);
}

__global__ __launch_bounds__(256, 6)
void warp_main(const float4* __restrict__ img, float4* __restrict__ out)
{
    const unsigned FULL = 0xffffffffu;
    int lane  = threadIdx.x & 31;
    int warp  = (blockIdx.x * blockDim.x + threadIdx.x) >> 5;
    int pbase = warp << 6;                 // 64 pixels per warp

    float4 imA = img[pbase + lane];
    float4 imB = img[pbase + 32 + lane];

    int cA, cB; unsigned wA, wB;
    prep(imA, cA, wA);
    prep(imB, cB, wB);

    int k = lane & 3;
    int g = lane >> 2;

    #pragma unroll
    for (int r = 0; r < 4; r++) {
        int q = r * 8 + g;

        int      cellA = __shfl_sync(FULL, cA, q);
        unsigned wAu   = __shfl_sync(FULL, wA, q);
        int      cellB = __shfl_sync(FULL, cB, q);
        unsigned wBu   = __shfl_sync(FULL, wB, q);

        uint4 vA = __ldg(&g_tab[(cellA << 2) + k]);
        uint4 vB = __ldg(&g_tab[(cellB << 2) + k]);

        int PA = pbase + q;
        int PB = pbase + 32 + q;
        float4 reA, reB;
        if (k == 2) { reA = __ldg(&img[PA]); reB = __ldg(&img[PB]); }

        float2 rA = bilin(vA, wAu);
        float2 rB = bilin(vB, wBu);

        float oAx = __shfl_xor_sync(FULL, rA.x, 2);
        float oAy = __shfl_xor_sync(FULL, rA.y, 2);
        float oBx = __shfl_xor_sync(FULL, rB.x, 2);
        float oBy = __shfl_xor_sync(FULL, rB.y, 2);

        float4 svA = (k == 2) ? reA : make_float4(rA.x, rA.y, oAx, oAy);
        float4 svB = (k == 2) ? reB : make_float4(rB.x, rB.y, oBx, oBy);
        if (k < 3) {
            out[(size_t)PA * 3 + k] = svA;
            out[(size_t)PB * 3 + k] = svB;
        }
    }
}

extern "C" void kernel_launch(void* const* d_in, const int* in_sizes, int n_in,
                              void* d_out, int out_size)
{
    const float4* img = (const float4*)d_in[0];
    const float*  wt  = (const float*)d_in[1];
    float4*       out = (float4*)d_out;

    build_tab<<<(NCELL * 4 + 255) / 256, 256>>>(wt);
    warp_main<<<NPIX / 512, 256>>>(img, out);
}

// round 10
// speedup vs baseline: 2.5044x; 1.0219x over previous
#include <cuda_runtime.h>
#include <cuda_fp16.h>
#include <math_constants.h>

// warpLayer, round 10: 2 px/thread; broadcast packs (cell16|w0q8|w1q8) into
// ONE word (PRMT+HFMA2 unpack); xor-exchange done on packed half2 accs.
// SHFL instructions per round: 8 -> 4.

#define NPIX  (16 * 512 * 512)
#define NCELL (255 * 255)

__device__ uint4 g_tab[NCELL * 4];   // 4.16 MB

__global__ __launch_bounds__(256)
void build_tab(const float* __restrict__ wt)
{
    int idx = blockIdx.x * blockDim.x + threadIdx.x;
    if (idx >= NCELL * 4) return;
    int cell = idx >> 2, k = idx & 3;
    int cp = (k == 1) ? 2 : (k == 2) ? 1 : k;   // perm {0,2,1,3}
    int i = cell / 255;
    int j = cell - i * 255;
    const float* base = wt + ((i << 8) + j) * 8 + (cp << 1);
    float2 c00 = *(const float2*)(base);
    float2 c01 = *(const float2*)(base + 8);
    float2 c10 = *(const float2*)(base + 256 * 8);
    float2 c11 = *(const float2*)(base + 256 * 8 + 8);
    const float S = 0.0005f;
    __half2 h00 = __floats2half2_rn(S * c00.x, S * c00.y);
    __half2 h01 = __floats2half2_rn(S * c01.x, S * c01.y);
    __half2 h10 = __floats2half2_rn(S * c10.x, S * c10.y);
    __half2 h11 = __floats2half2_rn(S * c11.x, S * c11.y);
    uint4 o;
    o.x = *reinterpret_cast<unsigned*>(&h00);
    o.y = *reinterpret_cast<unsigned*>(&h01);
    o.z = *reinterpret_cast<unsigned*>(&h10);
    o.w = *reinterpret_cast<unsigned*>(&h11);
    g_tab[idx] = o;
}

// C = wrap(atan2(y, x)) * 255/(2*pi) in [0, 255]
__device__ __forceinline__ float angle_c(float y, float x)
{
    const float K = 255.0f / (2.0f * CUDART_PI_F);
    float ax = fabsf(x), ay = fabsf(y);
    float mx = fmaxf(ax, ay), mn = fminf(ax, ay);
    float a  = __fdividef(mn, mx);
    float s  = a * a;
    float p  =            -0.01172120f;
    p = fmaf(p, s,  0.05265332f);
    p = fmaf(p, s, -0.11643287f);
    p = fmaf(p, s,  0.19354346f);
    p = fmaf(p, s, -0.33262347f);
    p = fmaf(p, s,  0.99997726f);
    float r = a * p * K;
    if (ay > ax)  r = 63.75f - r;
    if (x < 0.0f) r = 127.5f - r;
    if (y < 0.0f) r = 255.0f - r;
    return r;
}

// owner: pack (cell:16 | w0q:8 | w1q:8)
__device__ __forceinline__ unsigned prep(const float4& im)
{
    float c0 = fminf(angle_c(im.y, im.x), 254.0f);
    float c1 = fminf(angle_c(im.w, im.z), 254.0f);
    float fi = floorf(c0);
    float fj = floorf(c1);
    int cell = (int)fi * 255 + (int)fj;            // < 65025
    int w0q = min(__float2int_rn((c0 - fi) * 256.0f), 255);
    int w1q = min(__float2int_rn((c1 - fj) * 256.0f), 255);
    return ((unsigned)cell << 16) | ((unsigned)w0q << 8) | (unsigned)w1q;
}

// receiver: unpack w half2, bilinear on one 64B cell chunk, return packed half2
__device__ __forceinline__ unsigned bilin(const uint4& v, unsigned u)
{
    // bytes of u: b0=w1q, b1=w0q. build (0x64,w0q | 0x64,w1q) -> (1024+w0q, 1024+w1q)
    unsigned hb = __byte_perm(u, 0x64646464u, 0x4041);
    __half2 h = __hfma2(*reinterpret_cast<__half2*>(&hb),
                        __float2half2_rn(0.00390625f),      // 1/256
                        __float2half2_rn(-4.0f));           // (w0, w1)
    __half2 om = __hsub2(__float2half2_rn(1.0f), h);        // (1-w0, 1-w1)
    __half2 p  = __halves2half2(__high2half(om), __high2half(h)); // (1-w1, w1)
    __half2 A0 = __hmul2(__low2half2(om), p);   // (a00, a01)
    __half2 A1 = __hmul2(__low2half2(h),  p);   // (a10, a11)

    __half2 acc = __hmul2(__low2half2(A0),  *reinterpret_cast<const __half2*>(&v.x));
    acc = __hfma2(__high2half2(A0), *reinterpret_cast<const __half2*>(&v.y), acc);
    acc = __hfma2(__low2half2(A1),  *reinterpret_cast<const __half2*>(&v.z), acc);
    acc = __hfma2(__high2half2(A1), *reinterpret_cast<const __half2*>(&v.w), acc);
    return *reinterpret_cast<unsigned*>(&acc);
}

__global__ __launch_bounds__(256, 6)
void warp_main(const float4* __restrict__ img, float4* __restrict__ out)
{
    const unsigned FULL = 0xffffffffu;
    int lane  = threadIdx.x & 31;
    int warp  = (blockIdx.x * blockDim.x + threadIdx.x) >> 5;
    int pbase = warp << 6;                 // 64 pixels per warp

    float4 imA = img[pbase + lane];
    float4 imB = img[pbase + 32 + lane];

    unsigned uA = prep(imA);
    unsigned uB = prep(imB);

    int k = lane & 3;
    int g = lane >> 2;

    #pragma unroll
    for (int r = 0; r < 4; r++) {
        int q = r * 8 + g;

        unsigned bA = __shfl_sync(FULL, uA, q);
        unsigned bB = __shfl_sync(FULL, uB, q);

        uint4 vA = __ldg(&g_tab[((bA >> 16) << 2) + k]);
        uint4 vB = __ldg(&g_tab[((bB >> 16) << 2) + k]);

        int PA = pbase + q;
        int PB = pbase + 32 + q;
        float4 reA, reB;
        if (k == 2) { reA = __ldg(&img[PA]); reB = __ldg(&img[PB]); }

        unsigned accA = bilin(vA, bA);
        unsigned accB = bilin(vB, bB);

        // exchange packed half2 results: k=0<->2 (ch01<->ch23), k=1<->3 (ch45<->ch67)
        unsigned rxA = __shfl_xor_sync(FULL, accA, 2);
        unsigned rxB = __shfl_xor_sync(FULL, accB, 2);

        float2 oa = __half22float2(*reinterpret_cast<__half2*>(&accA));
        float2 ra = __half22float2(*reinterpret_cast<__half2*>(&rxA));
        float2 ob = __half22float2(*reinterpret_cast<__half2*>(&accB));
        float2 rb = __half22float2(*reinterpret_cast<__half2*>(&rxB));

        float4 svA = (k == 2) ? reA : make_float4(oa.x, oa.y, ra.x, ra.y);
        float4 svB = (k == 2) ? reB : make_float4(ob.x, ob.y, rb.x, rb.y);
        if (k < 3) {
            out[(size_t)PA * 3 + k] = svA;
            out[(size_t)PB * 3 + k] = svB;
        }
    }
}

extern "C" void kernel_launch(void* const* d_in, const int* in_sizes, int n_in,
                              void* d_out, int out_size)
{
    const float4* img = (const float4*)d_in[0];
    const float*  wt  = (const float*)d_in[1];
    float4*       out = (float4*)d_out;

    build_tab<<<(NCELL * 4 + 255) / 256, 256>>>(wt);
    warp_main<<<NPIX / 512, 256>>>(img, out);
}

// round 11
// speedup vs baseline: 2.5193x; 1.0059x over previous
#include <cuda_runtime.h>
#include <cuda_fp16.h>
#include <math_constants.h>

// warpLayer, round 11: R9 kernel + PDL overlap — warp_main launches
// concurrently with build_tab, runs its table-independent prologue
// (img load + atan2 + pack), then grid-dependency-syncs before gathers.

#define NPIX  (16 * 512 * 512)
#define NCELL (255 * 255)

__device__ uint4 g_tab[NCELL * 4];   // 4.16 MB

__global__ __launch_bounds__(256)
void build_tab(const float* __restrict__ wt)
{
    int idx = blockIdx.x * blockDim.x + threadIdx.x;
    if (idx < NCELL * 4) {
        int cell = idx >> 2, k = idx & 3;
        int cp = (k == 1) ? 2 : (k == 2) ? 1 : k;   // perm {0,2,1,3}
        int i = cell / 255;
        int j = cell - i * 255;
        const float* base = wt + ((i << 8) + j) * 8 + (cp << 1);
        float2 c00 = *(const float2*)(base);
        float2 c01 = *(const float2*)(base + 8);
        float2 c10 = *(const float2*)(base + 256 * 8);
        float2 c11 = *(const float2*)(base + 256 * 8 + 8);
        const float S = 0.0005f;
        __half2 h00 = __floats2half2_rn(S * c00.x, S * c00.y);
        __half2 h01 = __floats2half2_rn(S * c01.x, S * c01.y);
        __half2 h10 = __floats2half2_rn(S * c10.x, S * c10.y);
        __half2 h11 = __floats2half2_rn(S * c11.x, S * c11.y);
        uint4 o;
        o.x = *reinterpret_cast<unsigned*>(&h00);
        o.y = *reinterpret_cast<unsigned*>(&h01);
        o.z = *reinterpret_cast<unsigned*>(&h10);
        o.w = *reinterpret_cast<unsigned*>(&h11);
        g_tab[idx] = o;
    }
    cudaTriggerProgrammaticLaunchCompletion();
}

// C = wrap(atan2(y, x)) * 255/(2*pi) in [0, 255]
__device__ __forceinline__ float angle_c(float y, float x)
{
    const float K = 255.0f / (2.0f * CUDART_PI_F);
    float ax = fabsf(x), ay = fabsf(y);
    float mx = fmaxf(ax, ay), mn = fminf(ax, ay);
    float a  = __fdividef(mn, mx);
    float s  = a * a;
    float p  =            -0.01172120f;
    p = fmaf(p, s,  0.05265332f);
    p = fmaf(p, s, -0.11643287f);
    p = fmaf(p, s,  0.19354346f);
    p = fmaf(p, s, -0.33262347f);
    p = fmaf(p, s,  0.99997726f);
    float r = a * p * K;
    if (ay > ax)  r = 63.75f - r;
    if (x < 0.0f) r = 127.5f - r;
    if (y < 0.0f) r = 255.0f - r;
    return r;
}

// owner: pack (cell:16 | w0q:8 | w1q:8)
__device__ __forceinline__ unsigned prep(const float4& im)
{
    float c0 = fminf(angle_c(im.y, im.x), 254.0f);
    float c1 = fminf(angle_c(im.w, im.z), 254.0f);
    float fi = floorf(c0);
    float fj = floorf(c1);
    int cell = (int)fi * 255 + (int)fj;            // < 65025
    int w0q = min(__float2int_rn((c0 - fi) * 256.0f), 255);
    int w1q = min(__float2int_rn((c1 - fj) * 256.0f), 255);
    return ((unsigned)cell << 16) | ((unsigned)w0q << 8) | (unsigned)w1q;
}

// receiver: unpack w half2, bilinear on one 64B cell chunk, return packed half2
__device__ __forceinline__ unsigned bilin(const uint4& v, unsigned u)
{
    unsigned hb = __byte_perm(u, 0x64646464u, 0x4041);
    __half2 h = __hfma2(*reinterpret_cast<__half2*>(&hb),
                        __float2half2_rn(0.00390625f),      // 1/256
                        __float2half2_rn(-4.0f));           // (w0, w1)
    __half2 om = __hsub2(__float2half2_rn(1.0f), h);
    __half2 p  = __halves2half2(__high2half(om), __high2half(h));
    __half2 A0 = __hmul2(__low2half2(om), p);   // (a00, a01)
    __half2 A1 = __hmul2(__low2half2(h),  p);   // (a10, a11)

    __half2 acc = __hmul2(__low2half2(A0),  *reinterpret_cast<const __half2*>(&v.x));
    acc = __hfma2(__high2half2(A0), *reinterpret_cast<const __half2*>(&v.y), acc);
    acc = __hfma2(__low2half2(A1),  *reinterpret_cast<const __half2*>(&v.z), acc);
    acc = __hfma2(__high2half2(A1), *reinterpret_cast<const __half2*>(&v.w), acc);
    return *reinterpret_cast<unsigned*>(&acc);
}

__global__ __launch_bounds__(256, 6)
void warp_main(const float4* __restrict__ img, float4* __restrict__ out)
{
    const unsigned FULL = 0xffffffffu;
    int lane  = threadIdx.x & 31;
    int warp  = (blockIdx.x * blockDim.x + threadIdx.x) >> 5;
    int pbase = warp << 6;                 // 64 pixels per warp

    // ---- table-independent prologue (overlaps build_tab via PDL) ----
    float4 imA = img[pbase + lane];
    float4 imB = img[pbase + 32 + lane];

    unsigned uA = prep(imA);
    unsigned uB = prep(imB);

    // wait for build_tab's stores to be visible
    cudaGridDependencySynchronize();

    int k = lane & 3;
    int g = lane >> 2;

    #pragma unroll
    for (int r = 0; r < 4; r++) {
        int q = r * 8 + g;

        unsigned bA = __shfl_sync(FULL, uA, q);
        unsigned bB = __shfl_sync(FULL, uB, q);

        uint4 vA = __ldg(&g_tab[((bA >> 16) << 2) + k]);
        uint4 vB = __ldg(&g_tab[((bB >> 16) << 2) + k]);

        int PA = pbase + q;
        int PB = pbase + 32 + q;
        float4 reA, reB;
        if (k == 2) { reA = __ldg(&img[PA]); reB = __ldg(&img[PB]); }

        unsigned accA = bilin(vA, bA);
        unsigned accB = bilin(vB, bB);

        unsigned rxA = __shfl_xor_sync(FULL, accA, 2);
        unsigned rxB = __shfl_xor_sync(FULL, accB, 2);

        float2 oa = __half22float2(*reinterpret_cast<__half2*>(&accA));
        float2 ra = __half22float2(*reinterpret_cast<__half2*>(&rxA));
        float2 ob = __half22float2(*reinterpret_cast<__half2*>(&accB));
        float2 rb = __half22float2(*reinterpret_cast<__half2*>(&rxB));

        float4 svA = (k == 2) ? reA : make_float4(oa.x, oa.y, ra.x, ra.y);
        float4 svB = (k == 2) ? reB : make_float4(ob.x, ob.y, rb.x, rb.y);
        if (k < 3) {
            out[(size_t)PA * 3 + k] = svA;
            out[(size_t)PB * 3 + k] = svB;
        }
    }
}

extern "C" void kernel_launch(void* const* d_in, const int* in_sizes, int n_in,
                              void* d_out, int out_size)
{
    const float4* img = (const float4*)d_in[0];
    const float*  wt  = (const float*)d_in[1];
    float4*       out = (float4*)d_out;

    build_tab<<<(NCELL * 4 + 255) / 256, 256>>>(wt);

    // warp_main with programmatic stream serialization (PDL overlap)
    cudaLaunchConfig_t cfg = {};
    cfg.gridDim  = dim3(NPIX / 512, 1, 1);
    cfg.blockDim = dim3(256, 1, 1);
    cfg.dynamicSmemBytes = 0;
    cfg.stream = 0;
    cudaLaunchAttribute attr[1];
    attr[0].id = cudaLaunchAttributeProgrammaticStreamSerialization;
    attr[0].val.programmaticStreamSerializationAllowed = 1;
    cfg.attrs = attr;
    cfg.numAttrs = 1;
    cudaLaunchKernelEx(&cfg, warp_main, img, out);
}